// round 3
// baseline (speedup 1.0000x reference)
#include <cuda_runtime.h>
#include <cuda_bf16.h>
#include <cstdint>

// Problem constants
#define NB 4
#define NC 64
#define NHH 256
#define NWW 256
#define NH 63
#define NW 63
#define LPB (NH*NW)        // 3969 patches per image
#define M_TOT (NB*LPB)     // 15876
#define M_PAD 16000        // 125 tiles of 128
#define KDIM 4096
#define HID 256

// Scratch (static device globals — no allocation allowed)
static __device__ __nv_bfloat16 g_W1b[(size_t)HID*KDIM];            // 2 MB
static __device__ __nv_bfloat16 g_W2b[(size_t)KDIM*HID];            // 2 MB
static __device__ __nv_bfloat16 g_G[(size_t)M_PAD*HID];             // 8 MB
static __device__ __nv_bfloat16 g_img[(size_t)4*NB*NC*NHH*NWW];     // 134 MB (4 phase images)

// ---------------------------------------------------------------------------
// mma helpers
// ---------------------------------------------------------------------------
__device__ __forceinline__ void ldm4(uint32_t& r0, uint32_t& r1, uint32_t& r2, uint32_t& r3, uint32_t a){
  asm volatile("ldmatrix.sync.aligned.m8n8.x4.shared.b16 {%0,%1,%2,%3},[%4];\n"
    : "=r"(r0), "=r"(r1), "=r"(r2), "=r"(r3) : "r"(a));
}
__device__ __forceinline__ void mma_bf16(float* d, const uint32_t* a, const uint32_t* b){
  asm volatile("mma.sync.aligned.m16n8k16.row.col.f32.bf16.bf16.f32 "
    "{%0,%1,%2,%3},{%4,%5,%6,%7},{%8,%9},{%0,%1,%2,%3};\n"
    : "+f"(d[0]), "+f"(d[1]), "+f"(d[2]), "+f"(d[3])
    : "r"(a[0]), "r"(a[1]), "r"(a[2]), "r"(a[3]), "r"(b[0]), "r"(b[1]));
}

// smem tile: 128 rows x 4 chunks of 16B (BK=32 bf16). XOR swizzle: conflict-free
// ldmatrix (8 consecutive rows hit 8 distinct bank groups).
__device__ __forceinline__ int sw_idx(int row, int ch){ return row*4 + (ch ^ ((row>>1)&3)); }

__device__ __forceinline__ uint4 pack8(const float4& a, const float4& b){
  union { __nv_bfloat162 h[4]; uint4 u; } pk;
  pk.h[0] = __floats2bfloat162_rn(a.x, a.y);
  pk.h[1] = __floats2bfloat162_rn(a.z, a.w);
  pk.h[2] = __floats2bfloat162_rn(b.x, b.y);
  pk.h[3] = __floats2bfloat162_rn(b.z, b.w);
  return pk.u;
}

// Compute one BK=32 slab: 2 k16 steps, 2 m-tiles x 8 n-tiles per warp
__device__ __forceinline__ void compute_tile(const uint4* sA, const uint4* sB,
                                             int wm, int wn, int lane, float (*acc)[8][4]){
  uint32_t baseA = (uint32_t)__cvta_generic_to_shared(sA);
  uint32_t baseB = (uint32_t)__cvta_generic_to_shared(sB);
  #pragma unroll
  for (int ks = 0; ks < 2; ks++){
    uint32_t afr[2][4], bfr[8][2];
    #pragma unroll
    for (int mt = 0; mt < 2; mt++){
      int row = wm*32 + mt*16 + (lane & 15);
      int ch  = ks*2 + (lane >> 4);
      ldm4(afr[mt][0], afr[mt][1], afr[mt][2], afr[mt][3], baseA + (sw_idx(row, ch) << 4));
    }
    #pragma unroll
    for (int ntp = 0; ntp < 4; ntp++){
      int g   = lane >> 3;
      int row = wn*64 + ntp*16 + (g >> 1)*8 + (lane & 7);
      int ch  = ks*2 + (g & 1);
      ldm4(bfr[ntp*2][0], bfr[ntp*2][1], bfr[ntp*2+1][0], bfr[ntp*2+1][1],
           baseB + (sw_idx(row, ch) << 4));
    }
    #pragma unroll
    for (int mt = 0; mt < 2; mt++)
      #pragma unroll
      for (int nt = 0; nt < 8; nt++)
        mma_bf16(acc[mt][nt], afr[mt], bfr[nt]);
  }
}

// ---------------------------------------------------------------------------
// K0: weight conversion fp32 -> bf16
// ---------------------------------------------------------------------------
__global__ void k_convert(const float* __restrict__ W1, const float* __restrict__ W2){
  int idx = blockIdx.x*blockDim.x + threadIdx.x;
  if (idx < HID*KDIM){
    g_W1b[idx] = __float2bfloat16(W1[idx]);
    g_W2b[idx] = __float2bfloat16(W2[idx]);
  }
}

// ---------------------------------------------------------------------------
// K1: GEMM1 (implicit im2col) + bias + exact GELU -> G bf16 [M_PAD, 256]
//     G[l,n] = gelu( sum_k Pt[l,k] * W1[n,k] + b1[n] )
// ---------------------------------------------------------------------------
__global__ void __launch_bounds__(256, 2) k_gemm1(const float* __restrict__ x, const float* __restrict__ b1){
  __shared__ uint4 sA[2][512];
  __shared__ uint4 sB[2][512];
  const int tid  = threadIdx.x;
  const int lane = tid & 31, warp = tid >> 5;
  const int wm = warp & 3, wn = warp >> 2;
  const int l0 = blockIdx.y * 128;
  const int n0 = blockIdx.x * 128;

  // loader mapping: 4 threads per row (chunk = 16B), 2 rows per thread
  const int ch = tid & 3;
  const int rA = tid >> 2;   // 0..63
  int rowArr[2] = { rA, rA + 64 };
  const float* xbase[2];
  bool lval[2];
  #pragma unroll
  for (int q = 0; q < 2; q++){
    int l = l0 + rowArr[q];
    lval[q] = (l < M_TOT);
    int bb = 0, ph = 0, pw = 0;
    if (lval[q]){ bb = l / LPB; int rem = l - bb*LPB; ph = rem / NW; pw = rem - ph*NW; }
    xbase[q] = x + (((size_t)bb*NC)*NHH + (size_t)ph*4)*NWW + pw*4;
  }
  const __nv_bfloat16* w1p[2];
  #pragma unroll
  for (int q = 0; q < 2; q++) w1p[q] = g_W1b + (size_t)(n0 + rowArr[q])*KDIM + ch*8;

  float acc[2][8][4];
  #pragma unroll
  for (int a = 0; a < 2; a++)
    #pragma unroll
    for (int b = 0; b < 8; b++)
      #pragma unroll
      for (int c = 0; c < 4; c++) acc[a][b][c] = 0.f;

  float4 fa[4]; uint4 fb[2];

  // prologue: load slab 0
  {
    int k = ch*8;
    int c = k >> 6, kh = (k >> 3) & 7;
    #pragma unroll
    for (int q = 0; q < 2; q++){
      if (lval[q]){
        const float4* p = (const float4*)(xbase[q] + c*(NHH*NWW) + kh*NWW);
        fa[q*2] = p[0]; fa[q*2+1] = p[1];
      } else {
        fa[q*2] = make_float4(0,0,0,0); fa[q*2+1] = make_float4(0,0,0,0);
      }
      fb[q] = *(const uint4*)(w1p[q]);
    }
    #pragma unroll
    for (int q = 0; q < 2; q++){
      sA[0][sw_idx(rowArr[q], ch)] = pack8(fa[q*2], fa[q*2+1]);
      sB[0][sw_idx(rowArr[q], ch)] = fb[q];
    }
  }
  __syncthreads();

  const int KT = KDIM / 32;  // 128
  for (int kt = 0; kt < KT; kt++){
    int st = kt & 1;
    bool more = (kt + 1) < KT;
    if (more){
      int k = (kt+1)*32 + ch*8;
      int c = k >> 6, kh = (k >> 3) & 7;
      #pragma unroll
      for (int q = 0; q < 2; q++){
        if (lval[q]){
          const float4* p = (const float4*)(xbase[q] + c*(NHH*NWW) + kh*NWW);
          fa[q*2] = p[0]; fa[q*2+1] = p[1];
        } else {
          fa[q*2] = make_float4(0,0,0,0); fa[q*2+1] = make_float4(0,0,0,0);
        }
        fb[q] = *(const uint4*)(w1p[q] + (kt+1)*32);
      }
    }
    compute_tile(sA[st], sB[st], wm, wn, lane, acc);
    if (more){
      #pragma unroll
      for (int q = 0; q < 2; q++){
        sA[st^1][sw_idx(rowArr[q], ch)] = pack8(fa[q*2], fa[q*2+1]);
        sB[st^1][sw_idx(rowArr[q], ch)] = fb[q];
      }
    }
    __syncthreads();
  }

  // epilogue: bias + exact GELU -> G bf16 (padded rows written too: deterministic)
  #pragma unroll
  for (int mt = 0; mt < 2; mt++){
    #pragma unroll
    for (int hf = 0; hf < 2; hf++){
      int r = wm*32 + mt*16 + (lane >> 2) + hf*8;
      size_t l = (size_t)l0 + r;
      __nv_bfloat16* gp = g_G + l*HID;
      #pragma unroll
      for (int nt = 0; nt < 8; nt++){
        int n = n0 + wn*64 + nt*8 + (lane & 3)*2;
        float v0 = acc[mt][nt][hf*2+0] + b1[n];
        float v1 = acc[mt][nt][hf*2+1] + b1[n+1];
        v0 = 0.5f*v0*(1.f + erff(v0*0.70710678118654752f));
        v1 = 0.5f*v1*(1.f + erff(v1*0.70710678118654752f));
        *(__nv_bfloat162*)(gp + n) = __floats2bfloat162_rn(v0, v1);
      }
    }
  }
}

// ---------------------------------------------------------------------------
// K2: GEMM2  Y[l,n] = sum_h G[l,h]*W2[n,h] + b2[n], scattered into 4 phase
//     images img[dlt][b][c][i][j], dlt = (kh>=4)*2 + (kw>=4)
// ---------------------------------------------------------------------------
__global__ void __launch_bounds__(256, 2) k_gemm2(const float* __restrict__ b2){
  __shared__ uint4 sA[2][512];
  __shared__ uint4 sB[2][512];
  const int tid  = threadIdx.x;
  const int lane = tid & 31, warp = tid >> 5;
  const int wm = warp & 3, wn = warp >> 2;
  const int l0 = blockIdx.y * 128;
  const int n0 = blockIdx.x * 128;

  const int ch = tid & 3;
  const int rA = tid >> 2;
  int rowArr[2] = { rA, rA + 64 };
  const __nv_bfloat16* ga[2];
  const __nv_bfloat16* wb[2];
  #pragma unroll
  for (int q = 0; q < 2; q++){
    ga[q] = g_G   + (size_t)(l0 + rowArr[q])*HID + ch*8;   // l0+row < 16000, always valid
    wb[q] = g_W2b + (size_t)(n0 + rowArr[q])*HID + ch*8;
  }

  float acc[2][8][4];
  #pragma unroll
  for (int a = 0; a < 2; a++)
    #pragma unroll
    for (int b = 0; b < 8; b++)
      #pragma unroll
      for (int c = 0; c < 4; c++) acc[a][b][c] = 0.f;

  uint4 fA[2], fB[2];

  // prologue
  #pragma unroll
  for (int q = 0; q < 2; q++){
    fA[q] = *(const uint4*)(ga[q]);
    fB[q] = *(const uint4*)(wb[q]);
  }
  #pragma unroll
  for (int q = 0; q < 2; q++){
    sA[0][sw_idx(rowArr[q], ch)] = fA[q];
    sB[0][sw_idx(rowArr[q], ch)] = fB[q];
  }
  __syncthreads();

  const int KT = HID / 32;  // 8
  for (int kt = 0; kt < KT; kt++){
    int st = kt & 1;
    bool more = (kt + 1) < KT;
    if (more){
      #pragma unroll
      for (int q = 0; q < 2; q++){
        fA[q] = *(const uint4*)(ga[q] + (kt+1)*32);
        fB[q] = *(const uint4*)(wb[q] + (kt+1)*32);
      }
    }
    compute_tile(sA[st], sB[st], wm, wn, lane, acc);
    if (more){
      #pragma unroll
      for (int q = 0; q < 2; q++){
        sA[st^1][sw_idx(rowArr[q], ch)] = fA[q];
        sB[st^1][sw_idx(rowArr[q], ch)] = fB[q];
      }
    }
    __syncthreads();
  }

  // epilogue: bias, scatter to phase images (bf16x2 stores, same image per pair)
  #pragma unroll
  for (int mt = 0; mt < 2; mt++){
    #pragma unroll
    for (int hf = 0; hf < 2; hf++){
      int r = wm*32 + mt*16 + (lane >> 2) + hf*8;
      int l = l0 + r;
      if (l >= M_TOT) continue;
      int bb = l / LPB; int rem = l - bb*LPB;
      int ph = rem / NW; int pw = rem - ph*NW;
      #pragma unroll
      for (int nt = 0; nt < 8; nt++){
        int n  = n0 + wn*64 + nt*8 + (lane & 3)*2;
        int c  = n >> 6, kh = (n >> 3) & 7, kw = n & 7;  // kw even -> pair same phase
        int dlt = ((kh >> 2) << 1) | (kw >> 2);
        int i = ph*4 + kh;
        int j = pw*4 + kw;
        float v0 = acc[mt][nt][hf*2+0] + b2[n];
        float v1 = acc[mt][nt][hf*2+1] + b2[n+1];
        size_t idx = (((size_t)(dlt*NB + bb)*NC + c) << 16) + ((size_t)i << 8) + j;
        *(__nv_bfloat162*)(g_img + idx) = __floats2bfloat162_rn(v0, v1);
      }
    }
  }
}

// ---------------------------------------------------------------------------
// K3: blend  out = x + softplus(alpha_raw) * (sum of valid phase images)/norm
//     validity/norm computed analytically: dh=0 valid iff i<=251, dh=1 iff i>=4
// ---------------------------------------------------------------------------
__global__ void k_blend(const float* __restrict__ x, const float* __restrict__ alpha_raw,
                        float* __restrict__ out){
  size_t t = (size_t)blockIdx.x*blockDim.x + threadIdx.x;
  const size_t TOT = (size_t)NB*NC*NHH*NWW;
  if (t >= TOT) return;
  int j = (int)(t & 255), i = (int)((t >> 8) & 255);
  float ar = alpha_raw[0];
  float alpha = log1pf(expf(ar));
  bool h0 = (i <= 251), h1 = (i >= 4), w0 = (j <= 251), w1 = (j >= 4);
  float s = 0.f;
  if (h0 && w0) s += __bfloat162float(g_img[t]);
  if (h0 && w1) s += __bfloat162float(g_img[TOT + t]);
  if (h1 && w0) s += __bfloat162float(g_img[2*TOT + t]);
  if (h1 && w1) s += __bfloat162float(g_img[3*TOT + t]);
  float norm = (float)(((int)h0 + (int)h1) * ((int)w0 + (int)w1));
  out[t] = x[t] + alpha * s / norm;
}

// ---------------------------------------------------------------------------
extern "C" void kernel_launch(void* const* d_in, const int* in_sizes, int n_in,
                              void* d_out, int out_size){
  (void)in_sizes; (void)n_in; (void)out_size;
  const float* x         = (const float*)d_in[0];
  const float* W1        = (const float*)d_in[1];
  const float* b1        = (const float*)d_in[2];
  const float* W2        = (const float*)d_in[3];
  const float* b2        = (const float*)d_in[4];
  const float* alpha_raw = (const float*)d_in[5];
  float* out = (float*)d_out;

  k_convert<<<(HID*KDIM + 255)/256, 256>>>(W1, W2);
  k_gemm1<<<dim3(2, 125), 256>>>(x, b1);
  k_gemm2<<<dim3(32, 125), 256>>>(b2);
  k_blend<<<(int)(((size_t)NB*NC*NHH*NWW + 255)/256), 256>>>(x, alpha_raw, out);
}

// round 6
// speedup vs baseline: 1.0691x; 1.0691x over previous
#include <cuda_runtime.h>
#include <cuda_bf16.h>
#include <cstdint>

// Problem constants
#define NB 4
#define NC 64
#define NHH 256
#define NWW 256
#define NH 63
#define NW 63
#define LPB (NH*NW)        // 3969 patches per image
#define M_TOT (NB*LPB)     // 15876
#define M_PAD 16000        // 250 tiles of 64
#define KDIM 4096
#define HID 256
#define TOT ((size_t)NB*NC*NHH*NWW)   // 16777216

// Scratch (static device globals — no allocation allowed)
static __device__ __nv_bfloat16 g_W1b[(size_t)HID*KDIM];            // 2 MB
static __device__ __nv_bfloat16 g_W2b[(size_t)KDIM*HID];            // 2 MB
static __device__ __nv_bfloat16 g_xb[(size_t)TOT];                  // 32 MB (x in bf16)
static __device__ __nv_bfloat16 g_G[(size_t)M_PAD*HID];             // 8 MB
static __device__ __nv_bfloat16 g_img[(size_t)4*TOT];               // 134 MB (4 phase images)
static __device__ float g_alpha;

// ---------------------------------------------------------------------------
// mma helpers
// ---------------------------------------------------------------------------
__device__ __forceinline__ void ldm4(uint32_t& r0, uint32_t& r1, uint32_t& r2, uint32_t& r3, uint32_t a){
  asm volatile("ldmatrix.sync.aligned.m8n8.x4.shared.b16 {%0,%1,%2,%3},[%4];\n"
    : "=r"(r0), "=r"(r1), "=r"(r2), "=r"(r3) : "r"(a));
}
__device__ __forceinline__ void mma_bf16(float* d, const uint32_t* a, const uint32_t* b){
  asm volatile("mma.sync.aligned.m16n8k16.row.col.f32.bf16.bf16.f32 "
    "{%0,%1,%2,%3},{%4,%5,%6,%7},{%8,%9},{%0,%1,%2,%3};\n"
    : "+f"(d[0]), "+f"(d[1]), "+f"(d[2]), "+f"(d[3])
    : "r"(a[0]), "r"(a[1]), "r"(a[2]), "r"(a[3]), "r"(b[0]), "r"(b[1]));
}

// smem tile: rows x 4 chunks of 16B (BK=32 bf16). XOR swizzle: conflict-free ldmatrix.
__device__ __forceinline__ int sw_idx(int row, int ch){ return row*4 + (ch ^ ((row>>1)&3)); }

// Compute one BK=32 slab per warp: 2 k16 steps, 2 m-tiles (32 rows) x 8 n-tiles (64 cols).
// Block tile: BM=64 (wm in {0,1}), BN=256 (wn in {0..3}).
__device__ __forceinline__ void compute_tile(const uint4* sA, const uint4* sB,
                                             int wm, int wn, int lane, float (*acc)[8][4]){
  uint32_t baseA = (uint32_t)__cvta_generic_to_shared(sA);
  uint32_t baseB = (uint32_t)__cvta_generic_to_shared(sB);
  #pragma unroll
  for (int ks = 0; ks < 2; ks++){
    uint32_t afr[2][4], bfr[8][2];
    #pragma unroll
    for (int mt = 0; mt < 2; mt++){
      int row = wm*32 + mt*16 + (lane & 15);
      int ch  = ks*2 + (lane >> 4);
      ldm4(afr[mt][0], afr[mt][1], afr[mt][2], afr[mt][3], baseA + (sw_idx(row, ch) << 4));
    }
    #pragma unroll
    for (int ntp = 0; ntp < 4; ntp++){
      int g   = lane >> 3;
      int row = wn*64 + ntp*16 + (g >> 1)*8 + (lane & 7);
      int ch  = ks*2 + (g & 1);
      ldm4(bfr[ntp*2][0], bfr[ntp*2][1], bfr[ntp*2+1][0], bfr[ntp*2+1][1],
           baseB + (sw_idx(row, ch) << 4));
    }
    #pragma unroll
    for (int mt = 0; mt < 2; mt++)
      #pragma unroll
      for (int nt = 0; nt < 8; nt++)
        mma_bf16(acc[mt][nt], afr[mt], bfr[nt]);
  }
}

// ---------------------------------------------------------------------------
// K0a: weight conversion fp32 -> bf16 (x4 vectorized) + alpha
// ---------------------------------------------------------------------------
__global__ void k_convert(const float* __restrict__ W1, const float* __restrict__ W2,
                          const float* __restrict__ alpha_raw){
  int t = blockIdx.x*blockDim.x + threadIdx.x;
  if (t == 0) g_alpha = log1pf(expf(alpha_raw[0]));
  if (t < HID*KDIM/4){
    float4 a = ((const float4*)W1)[t];
    float4 b = ((const float4*)W2)[t];
    uint2 pa, pb;
    *(__nv_bfloat162*)&pa.x = __floats2bfloat162_rn(a.x, a.y);
    *(__nv_bfloat162*)&pa.y = __floats2bfloat162_rn(a.z, a.w);
    *(__nv_bfloat162*)&pb.x = __floats2bfloat162_rn(b.x, b.y);
    *(__nv_bfloat162*)&pb.y = __floats2bfloat162_rn(b.z, b.w);
    ((uint2*)g_W1b)[t] = pa;
    ((uint2*)g_W2b)[t] = pb;
  }
}

// K0b: x fp32 -> bf16 (x4 vectorized)
__global__ void k_convx(const float* __restrict__ x){
  size_t t = (size_t)blockIdx.x*blockDim.x + threadIdx.x;
  if (t < TOT/4){
    float4 a = ((const float4*)x)[t];
    uint2 p;
    *(__nv_bfloat162*)&p.x = __floats2bfloat162_rn(a.x, a.y);
    *(__nv_bfloat162*)&p.y = __floats2bfloat162_rn(a.z, a.w);
    ((uint2*)g_xb)[t] = p;
  }
}

// ---------------------------------------------------------------------------
// K1: GEMM1 (implicit im2col from g_xb) + bias + exact GELU -> G bf16 [M_PAD,256]
//     block tile 64(M) x 256(N), K=4096
// ---------------------------------------------------------------------------
__global__ void __launch_bounds__(256, 2) k_gemm1(const float* __restrict__ b1){
  __shared__ uint4 sA[2][256];    // 64 rows x 4 chunks
  __shared__ uint4 sB[2][1024];   // 256 rows x 4 chunks
  const int tid  = threadIdx.x;
  const int lane = tid & 31, warp = tid >> 5;
  const int wm = warp & 1, wn = warp >> 1;
  const int l0 = blockIdx.y * 64;

  const int ch = tid & 3;
  const int rr = tid >> 2;        // 0..63: A row, and B row group base
  // A source (im2col position)
  const int l = l0 + rr;
  const bool lval = (l < M_TOT);
  const __nv_bfloat16* xbase = g_xb;
  {
    int bb = 0, ph = 0, pw = 0;
    if (lval){ bb = l / LPB; int rem = l - bb*LPB; ph = rem / NW; pw = rem - ph*NW; }
    xbase = g_xb + (((size_t)bb*NC)*NHH + (size_t)ph*4)*NWW + pw*4;
  }
  // B rows: rr, rr+64, rr+128, rr+192 of W1 (N=HID=256)
  const __nv_bfloat16* wp[4];
  #pragma unroll
  for (int q = 0; q < 4; q++) wp[q] = g_W1b + (size_t)(rr + 64*q)*KDIM + ch*8;

  float acc[2][8][4];
  #pragma unroll
  for (int a = 0; a < 2; a++)
    #pragma unroll
    for (int b = 0; b < 8; b++)
      #pragma unroll
      for (int c = 0; c < 4; c++) acc[a][b][c] = 0.f;

  uint2 a0, a1; uint4 fb[4];

  // prologue: load slab 0
  {
    int k = ch*8;
    int c = k >> 6, kh = (k >> 3) & 7;
    a0 = make_uint2(0,0); a1 = make_uint2(0,0);
    if (lval){
      const __nv_bfloat16* p = xbase + c*(NHH*NWW) + kh*NWW;
      a0 = *(const uint2*)(p);
      a1 = *(const uint2*)(p + 4);
    }
    #pragma unroll
    for (int q = 0; q < 4; q++) fb[q] = *(const uint4*)(wp[q]);
    sA[0][sw_idx(rr, ch)] = make_uint4(a0.x, a0.y, a1.x, a1.y);
    #pragma unroll
    for (int q = 0; q < 4; q++) sB[0][sw_idx(rr + 64*q, ch)] = fb[q];
  }
  __syncthreads();

  const int KT = KDIM / 32;  // 128
  for (int kt = 0; kt < KT; kt++){
    int st = kt & 1;
    bool more = (kt + 1) < KT;
    if (more){
      int k = (kt+1)*32 + ch*8;
      int c = k >> 6, kh = (k >> 3) & 7;
      a0 = make_uint2(0,0); a1 = make_uint2(0,0);
      if (lval){
        const __nv_bfloat16* p = xbase + c*(NHH*NWW) + kh*NWW;
        a0 = *(const uint2*)(p);
        a1 = *(const uint2*)(p + 4);
      }
      #pragma unroll
      for (int q = 0; q < 4; q++) fb[q] = *(const uint4*)(wp[q] + (kt+1)*32);
    }
    compute_tile(sA[st], sB[st], wm, wn, lane, acc);
    if (more){
      sA[st^1][sw_idx(rr, ch)] = make_uint4(a0.x, a0.y, a1.x, a1.y);
      #pragma unroll
      for (int q = 0; q < 4; q++) sB[st^1][sw_idx(rr + 64*q, ch)] = fb[q];
    }
    __syncthreads();
  }

  // epilogue: bias + exact GELU -> G bf16 (padded rows written too: deterministic)
  #pragma unroll
  for (int mt = 0; mt < 2; mt++){
    #pragma unroll
    for (int hf = 0; hf < 2; hf++){
      int r = wm*32 + mt*16 + (lane >> 2) + hf*8;
      size_t ll = (size_t)l0 + r;
      __nv_bfloat16* gp = g_G + ll*HID;
      #pragma unroll
      for (int nt = 0; nt < 8; nt++){
        int n = wn*64 + nt*8 + (lane & 3)*2;
        float v0 = acc[mt][nt][hf*2+0] + b1[n];
        float v1 = acc[mt][nt][hf*2+1] + b1[n+1];
        v0 = 0.5f*v0*(1.f + erff(v0*0.70710678118654752f));
        v1 = 0.5f*v1*(1.f + erff(v1*0.70710678118654752f));
        *(__nv_bfloat162*)(gp + n) = __floats2bfloat162_rn(v0, v1);
      }
    }
  }
}

// ---------------------------------------------------------------------------
// K2: GEMM2  Y[l,n] = sum_h G[l,h]*W2[n,h] + b2[n], scattered into 4 phase
//     images img[dlt][b][c][i][j], dlt = (kh>=4)*2 + (kw>=4)
//     block tile 64(M) x 256(N), K=256
// ---------------------------------------------------------------------------
__global__ void __launch_bounds__(256, 2) k_gemm2(const float* __restrict__ b2){
  __shared__ uint4 sA[2][256];
  __shared__ uint4 sB[2][1024];
  const int tid  = threadIdx.x;
  const int lane = tid & 31, warp = tid >> 5;
  const int wm = warp & 1, wn = warp >> 1;
  const int l0 = blockIdx.y * 64;
  const int n0 = blockIdx.x * 256;

  const int ch = tid & 3;
  const int rr = tid >> 2;
  const __nv_bfloat16* ga = g_G + (size_t)(l0 + rr)*HID + ch*8;   // l0+rr <= 15999, valid
  const __nv_bfloat16* wp[4];
  #pragma unroll
  for (int q = 0; q < 4; q++) wp[q] = g_W2b + (size_t)(n0 + rr + 64*q)*HID + ch*8;

  float acc[2][8][4];
  #pragma unroll
  for (int a = 0; a < 2; a++)
    #pragma unroll
    for (int b = 0; b < 8; b++)
      #pragma unroll
      for (int c = 0; c < 4; c++) acc[a][b][c] = 0.f;

  uint4 fA, fb[4];

  // prologue
  fA = *(const uint4*)(ga);
  #pragma unroll
  for (int q = 0; q < 4; q++) fb[q] = *(const uint4*)(wp[q]);
  sA[0][sw_idx(rr, ch)] = fA;
  #pragma unroll
  for (int q = 0; q < 4; q++) sB[0][sw_idx(rr + 64*q, ch)] = fb[q];
  __syncthreads();

  const int KT = HID / 32;  // 8
  for (int kt = 0; kt < KT; kt++){
    int st = kt & 1;
    bool more = (kt + 1) < KT;
    if (more){
      fA = *(const uint4*)(ga + (kt+1)*32);
      #pragma unroll
      for (int q = 0; q < 4; q++) fb[q] = *(const uint4*)(wp[q] + (kt+1)*32);
    }
    compute_tile(sA[st], sB[st], wm, wn, lane, acc);
    if (more){
      sA[st^1][sw_idx(rr, ch)] = fA;
      #pragma unroll
      for (int q = 0; q < 4; q++) sB[st^1][sw_idx(rr + 64*q, ch)] = fb[q];
    }
    __syncthreads();
  }

  // epilogue: bias, scatter to phase images (bf16x2 stores; kw pair shares phase)
  #pragma unroll
  for (int mt = 0; mt < 2; mt++){
    #pragma unroll
    for (int hf = 0; hf < 2; hf++){
      int r = wm*32 + mt*16 + (lane >> 2) + hf*8;
      int l = l0 + r;
      if (l >= M_TOT) continue;
      int bb = l / LPB; int rem = l - bb*LPB;
      int ph = rem / NW; int pw = rem - ph*NW;
      #pragma unroll
      for (int nt = 0; nt < 8; nt++){
        int n  = n0 + wn*64 + nt*8 + (lane & 3)*2;
        int c  = n >> 6, kh = (n >> 3) & 7, kw = n & 7;
        int dlt = ((kh >> 2) << 1) | (kw >> 2);
        int i = ph*4 + kh;
        int j = pw*4 + kw;
        float v0 = acc[mt][nt][hf*2+0] + b2[n];
        float v1 = acc[mt][nt][hf*2+1] + b2[n+1];
        size_t idx = (((size_t)(dlt*NB + bb)*NC + c) << 16) + ((size_t)i << 8) + j;
        *(__nv_bfloat162*)(g_img + idx) = __floats2bfloat162_rn(v0, v1);
      }
    }
  }
}

// ---------------------------------------------------------------------------
// K3: blend  out = x + alpha * (sum of valid phase images)/norm
//     4 elements per thread; validity uniform per 4-vector (boundaries 4-aligned)
// ---------------------------------------------------------------------------
__global__ void k_blend(const float* __restrict__ x, float* __restrict__ out){
  size_t t = (size_t)blockIdx.x*blockDim.x + threadIdx.x;
  if (t >= TOT/4) return;
  size_t e = t*4;
  int j0 = (int)(e & 255);
  int i  = (int)((e >> 8) & 255);
  bool h0 = (i <= 251), h1 = (i >= 4), w0 = (j0 < 252), w1 = (j0 >= 4);

  float4 xv = *(const float4*)(x + e);
  float s0 = 0.f, s1 = 0.f, s2 = 0.f, s3 = 0.f;
  #pragma unroll
  for (int d = 0; d < 4; d++){
    bool v = (d == 0) ? (h0 && w0) : (d == 1) ? (h0 && w1) : (d == 2) ? (h1 && w0) : (h1 && w1);
    if (v){
      uint2 p = *(const uint2*)(g_img + (size_t)d*TOT + e);
      float2 f0 = __bfloat1622float2(*(const __nv_bfloat162*)&p.x);
      float2 f1 = __bfloat1622float2(*(const __nv_bfloat162*)&p.y);
      s0 += f0.x; s1 += f0.y; s2 += f1.x; s3 += f1.y;
    }
  }
  // per-axis count in {1,2}; inverse is exact power of two
  float scale = g_alpha * (((h0 && h1) ? 0.5f : 1.0f) * ((w0 && w1) ? 0.5f : 1.0f));
  float4 ov;
  ov.x = xv.x + scale * s0;
  ov.y = xv.y + scale * s1;
  ov.z = xv.z + scale * s2;
  ov.w = xv.w + scale * s3;
  *(float4*)(out + e) = ov;
}

// ---------------------------------------------------------------------------
extern "C" void kernel_launch(void* const* d_in, const int* in_sizes, int n_in,
                              void* d_out, int out_size){
  (void)in_sizes; (void)n_in; (void)out_size;
  const float* x         = (const float*)d_in[0];
  const float* W1        = (const float*)d_in[1];
  const float* b1        = (const float*)d_in[2];
  const float* W2        = (const float*)d_in[3];
  const float* b2        = (const float*)d_in[4];
  const float* alpha_raw = (const float*)d_in[5];
  float* out = (float*)d_out;

  k_convert<<<(HID*KDIM/4 + 255)/256, 256>>>(W1, W2, alpha_raw);
  k_convx<<<(int)((TOT/4 + 255)/256), 256>>>(x);
  k_gemm1<<<dim3(1, 250), 256>>>(b1);
  k_gemm2<<<dim3(16, 250), 256>>>(b2);
  k_blend<<<(int)((TOT/4 + 255)/256), 256>>>(x, out);
}